// round 6
// baseline (speedup 1.0000x reference)
#include <cuda_runtime.h>
#include <math.h>

#define BB 256
#define SS 512
#define VV 768
#define TT 513   // S + mean row
#define HH 50
#define NSPLIT 8
#define SCHUNK 64   // SS / NSPLIT

// ---------------- scratch (device globals; no allocation allowed) ----------------
__device__ __align__(16) float g_mean1[BB * VV];
__device__ __align__(16) float g_mean2[BB * VV];
__device__ __align__(16) float g_part1[NSPLIT * BB * VV];   // sum1 partials
__device__ __align__(16) float g_part2[NSPLIT * BB * VV];   // sum2 partials
__device__ __align__(16) float g_row[BB * TT];              // row[b,t] = mean1[b] . x2[b,t]
__device__ float g_rowsum[NSPLIT * BB];                     // per-chunk sums of row dots
__device__ __align__(16) float g_wy[BB * TT];               // batch-softmax weights
__device__ __align__(16) float g_axpart[NSPLIT * BB * VV];  // online-softmax partial accumulators
__device__ float g_axm[NSPLIT * BB];                        // running max per partial
__device__ float g_axz[NSPLIT * BB];                        // running Z per partial
__device__ __align__(16) float g_aypart[NSPLIT * BB * VV];  // atty partial sums

// ---------------- K1: partial sum of output_1 over s (unroll-8, split accumulators) ----------------
__global__ __launch_bounds__(192) void meanPartK(const float* __restrict__ src) {
    int split = blockIdx.x, b = blockIdx.y, tid = threadIdx.x;  // block = 192 = VV/4
    const float4* s4 = (const float4*)src;
    float4 a0 = make_float4(0.f, 0.f, 0.f, 0.f);
    float4 a1 = make_float4(0.f, 0.f, 0.f, 0.f);
    size_t base = ((size_t)b * SS + (size_t)split * SCHUNK) * (VV / 4) + tid;
    for (int t = 0; t < SCHUNK; t += 8) {
        float4 x[8];
#pragma unroll
        for (int k = 0; k < 8; k++) x[k] = __ldcs(&s4[base + (size_t)(t + k) * (VV / 4)]);
#pragma unroll
        for (int k = 0; k < 8; k += 2) {
            a0.x += x[k].x;   a0.y += x[k].y;   a0.z += x[k].z;   a0.w += x[k].w;
            a1.x += x[k+1].x; a1.y += x[k+1].y; a1.z += x[k+1].z; a1.w += x[k+1].w;
        }
    }
    a0.x += a1.x; a0.y += a1.y; a0.z += a1.z; a0.w += a1.w;
    ((float4*)g_part1)[((size_t)split * BB + b) * (VV / 4) + tid] = a0;
}

// ---------------- K2: fused pass over output_2: sum2 partials + row[b,t] dots + chunk dot-sums ----------------
__global__ __launch_bounds__(256) void meanRowPartK(const float* __restrict__ src) {
    __shared__ __align__(16) float m_s[VV];
    __shared__ __align__(16) float buf[VV];
    __shared__ float sdot[SCHUNK];
    int split = blockIdx.x, b = blockIdx.y, tid = threadIdx.x;
    int wid = tid >> 5, lane = tid & 31;
    // mean1 from partials (L2-hot)
    for (int i = tid; i < VV; i += 256) {
        float s = 0.f;
#pragma unroll
        for (int p = 0; p < NSPLIT; p++) s += g_part1[((size_t)p * BB + b) * VV + i];
        m_s[i] = s * (1.0f / SS);
    }
    __syncthreads();
    const float4* s4 = (const float4*)src;
    const float4* m4 = (const float4*)m_s;
    float4 macc[6];
#pragma unroll
    for (int j = 0; j < 6; j++) macc[j] = make_float4(0.f, 0.f, 0.f, 0.f);
    int t0 = split * SCHUNK;
    for (int i = 0; i < SCHUNK / 8; i++) {
        int t = t0 + wid + 8 * i;
        size_t base = ((size_t)b * SS + t) * (VV / 4);
        float dot = 0.f;
#pragma unroll
        for (int j = 0; j < 6; j++) {
            float4 x = __ldcs(&s4[base + lane + 32 * j]);
            float4 m = m4[lane + 32 * j];
            dot += x.x * m.x + x.y * m.y + x.z * m.z + x.w * m.w;
            macc[j].x += x.x; macc[j].y += x.y; macc[j].z += x.z; macc[j].w += x.w;
        }
#pragma unroll
        for (int o = 16; o; o >>= 1) dot += __shfl_xor_sync(0xffffffffu, dot, o);
        if (lane == 0) { g_row[b * TT + t] = dot; sdot[wid + 8 * i] = dot; }
    }
    // cross-warp reduce of per-lane column partial sums
    float4* b4 = (float4*)buf;
    for (int w = 0; w < 8; w++) {
        if (wid == w) {
#pragma unroll
            for (int j = 0; j < 6; j++) {
                if (w == 0) b4[lane + 32 * j] = macc[j];
                else {
                    float4 t2 = b4[lane + 32 * j];
                    t2.x += macc[j].x; t2.y += macc[j].y; t2.z += macc[j].z; t2.w += macc[j].w;
                    b4[lane + 32 * j] = t2;
                }
            }
        }
        __syncthreads();
    }
    for (int i = tid; i < VV; i += 256) g_part2[((size_t)split * BB + b) * VV + i] = buf[i];
    // chunk sum of the SCHUNK dots -> g_rowsum (for row[b,512] = mean of all dots)
    if (tid < 32) {
        float s = sdot[tid] + sdot[tid + 32];
#pragma unroll
        for (int o = 16; o; o >>= 1) s += __shfl_xor_sync(0xffffffffu, s, o);
        if (tid == 0) g_rowsum[split * BB + b] = s;
    }
}

// ---------------- K3 (fused): blocks [0,513): softmax over batch per t (t=512 builds its row first)
//                              blocks [513,769): materialize mean1/mean2 for b = blk-513 ----------------
__global__ __launch_bounds__(256) void midK() {
    if (blockIdx.x >= TT) {
        int b = blockIdx.x - TT, tid = threadIdx.x;
        for (int i = tid; i < VV; i += 256) {
            float s1 = 0.f, s2 = 0.f;
#pragma unroll
            for (int p = 0; p < NSPLIT; p++) {
                s1 += g_part1[((size_t)p * BB + b) * VV + i];
                s2 += g_part2[((size_t)p * BB + b) * VV + i];
            }
            g_mean1[(size_t)b * VV + i] = s1 * (1.0f / SS);
            g_mean2[(size_t)b * VV + i] = s2 * (1.0f / SS);
        }
        return;
    }
    int t = blockIdx.x;          // [0, TT)
    int b = threadIdx.x;         // block = BB
    __shared__ float red[BB];
    float v;
    if (t == 512) {
        float s = 0.f;
#pragma unroll
        for (int p = 0; p < NSPLIT; p++) s += g_rowsum[p * BB + b];
        v = s * (1.0f / SS);
        g_row[b * TT + 512] = v;   // finalK needs col512
    } else {
        v = g_row[b * TT + t];
    }
    red[b] = v; __syncthreads();
    for (int o = 128; o; o >>= 1) { if (b < o) red[b] = fmaxf(red[b], red[b + o]); __syncthreads(); }
    float m = red[0]; __syncthreads();
    float e = __expf(v - m);
    red[b] = e; __syncthreads();
    for (int o = 128; o; o >>= 1) { if (b < o) red[b] += red[b + o]; __syncthreads(); }
    float Z = red[0];
    g_wy[b * TT + t] = e / Z;
}

// ---------------- K4 (fused): z=0 attx over output_1 (warp-per-row online softmax, barrier-free)
//                              z=1 atty over output_2 (weighted sum, unroll 8) ----------------
__global__ __launch_bounds__(256) void attK(const float* __restrict__ out1, const float* __restrict__ out2) {
    __shared__ __align__(16) float sacc[8 * VV];   // per-warp partial accumulators
    __shared__ float sm_m[8], sm_z[8];
    __shared__ float wy_s[SCHUNK];
    int split = blockIdx.x, b = blockIdx.y, tid = threadIdx.x;
    int wid = tid >> 5, lane = tid & 31;

    if (blockIdx.z == 1) {
        // ---- atty: acc[v] += wy[t] * out2[b,t,v] ----
        int t0 = split * SCHUNK;
        if (tid < SCHUNK) wy_s[tid] = g_wy[b * TT + t0 + tid];
        __syncthreads();
        if (tid < VV / 4) {
            const float4* s4 = (const float4*)out2;
            float4 a0 = make_float4(0.f, 0.f, 0.f, 0.f);
            float4 a1 = make_float4(0.f, 0.f, 0.f, 0.f);
            size_t base = ((size_t)b * SS + t0) * (VV / 4) + tid;
            for (int t = 0; t < SCHUNK; t += 8) {
                float4 x[8]; float w[8];
#pragma unroll
                for (int k = 0; k < 8; k++) { x[k] = __ldcs(&s4[base + (size_t)(t + k) * (VV / 4)]); w[k] = wy_s[t + k]; }
#pragma unroll
                for (int k = 0; k < 8; k += 2) {
                    a0.x += w[k] * x[k].x;     a0.y += w[k] * x[k].y;     a0.z += w[k] * x[k].z;     a0.w += w[k] * x[k].w;
                    a1.x += w[k+1] * x[k+1].x; a1.y += w[k+1] * x[k+1].y; a1.z += w[k+1] * x[k+1].z; a1.w += w[k+1] * x[k+1].w;
                }
            }
            a0.x += a1.x; a0.y += a1.y; a0.z += a1.z; a0.w += a1.w;
            ((float4*)g_aypart)[((size_t)split * BB + b) * (VV / 4) + tid] = a0;
        }
        return;
    }

    // ---- attx: warp-per-row online softmax over s of (out1[b,s,:] . mean2[b]) ----
    const float4* s4 = (const float4*)out1;
    const float4* m4 = (const float4*)g_mean2 + (size_t)b * (VV / 4);
    float4 m[6];
#pragma unroll
    for (int j = 0; j < 6; j++) m[j] = m4[lane + 32 * j];
    float4 acc[6];
#pragma unroll
    for (int j = 0; j < 6; j++) acc[j] = make_float4(0.f, 0.f, 0.f, 0.f);
    float runmax = -1e30f, Z = 0.f;
    int s0 = split * SCHUNK + wid * (SCHUNK / 8);   // 8 rows per warp

    for (int i = 0; i < SCHUNK / 8; i++) {
        size_t base = ((size_t)b * SS + s0 + i) * (VV / 4);
        float4 x[6];
#pragma unroll
        for (int j = 0; j < 6; j++) x[j] = __ldcs(&s4[base + lane + 32 * j]);
        float dot = 0.f;
#pragma unroll
        for (int j = 0; j < 6; j++)
            dot += x[j].x * m[j].x + x[j].y * m[j].y + x[j].z * m[j].z + x[j].w * m[j].w;
#pragma unroll
        for (int o = 16; o; o >>= 1) dot += __shfl_xor_sync(0xffffffffu, dot, o);
        if (dot > runmax) {   // warp-uniform, rare
            float sc = __expf(runmax - dot);
            Z *= sc;
#pragma unroll
            for (int j = 0; j < 6; j++) {
                acc[j].x *= sc; acc[j].y *= sc; acc[j].z *= sc; acc[j].w *= sc;
            }
            runmax = dot;
        }
        float w = __expf(dot - runmax);
        Z += w;
#pragma unroll
        for (int j = 0; j < 6; j++) {
            acc[j].x += w * x[j].x; acc[j].y += w * x[j].y; acc[j].z += w * x[j].z; acc[j].w += w * x[j].w;
        }
    }
    // single-barrier cross-warp merge
    float4* sa4 = (float4*)sacc;
#pragma unroll
    for (int j = 0; j < 6; j++) sa4[wid * (VV / 4) + lane + 32 * j] = acc[j];
    if (lane == 0) { sm_m[wid] = runmax; sm_z[wid] = Z; }
    __syncthreads();
    float M = sm_m[0];
#pragma unroll
    for (int w = 1; w < 8; w++) M = fmaxf(M, sm_m[w]);
    float ew[8];
#pragma unroll
    for (int w = 0; w < 8; w++) ew[w] = __expf(sm_m[w] - M);
    size_t ob = (size_t)split * BB + b;
#pragma unroll
    for (int r = 0; r < 3; r++) {
        int v = tid + 256 * r;
        float s = 0.f;
#pragma unroll
        for (int w = 0; w < 8; w++) s += ew[w] * sacc[w * VV + v];
        g_axpart[ob * VV + v] = s;
    }
    if (tid == 0) {
        float Zc = 0.f;
#pragma unroll
        for (int w = 0; w < 8; w++) Zc += ew[w] * sm_z[w];
        g_axm[ob] = M; g_axz[ob] = Zc;
    }
}

// ---------------- K5: combine partials + full MLP head ----------------
__global__ __launch_bounds__(256) void finalK(const float* __restrict__ Wg, const float* __restrict__ bg,
                                              const float* __restrict__ Wfd, const float* __restrict__ bfd,
                                              const float* __restrict__ Wff, const float* __restrict__ bff,
                                              float* __restrict__ out) {
    int b = blockIdx.x, tid = threadIdx.x, wid = tid >> 5, lane = tid & 31;
    __shared__ float c1[2 * VV];   // [mean1 , atty]
    __shared__ float c2[2 * VV];   // [mean2 , attx]
    __shared__ float o_s[2 * HH];
    __shared__ float h_s[HH];
    float col512 = g_row[b * TT + 512];
    float wy512 = g_wy[b * TT + 512];
    float m[NSPLIT], z[NSPLIT];
#pragma unroll
    for (int i = 0; i < NSPLIT; i++) { m[i] = g_axm[i * BB + b]; z[i] = g_axz[i * BB + b]; }
    float M = col512;
#pragma unroll
    for (int i = 0; i < NSPLIT; i++) M = fmaxf(M, m[i]);
    float e5 = __expf(col512 - M);
    float Ztot = e5;
    float e[NSPLIT];
#pragma unroll
    for (int i = 0; i < NSPLIT; i++) { e[i] = __expf(m[i] - M); Ztot += e[i] * z[i]; }
    float inv = 1.f / Ztot;
    for (int v = tid; v < VV; v += 256) {
        float m1v = g_mean1[(size_t)b * VV + v];
        float m2v = g_mean2[(size_t)b * VV + v];
        float ax = e5 * m1v;
        float ay = wy512 * m2v;
#pragma unroll
        for (int i = 0; i < NSPLIT; i++) {
            ax += e[i] * g_axpart[((size_t)i * BB + b) * VV + v];
            ay += g_aypart[((size_t)i * BB + b) * VV + v];
        }
        c1[v] = m1v; c1[VV + v] = ay;
        c2[v] = m2v; c2[VV + v] = ax * inv;
    }
    __syncthreads();
    // o1/o2: 100 dot products of length 1536 against Wg rows
    for (int task = wid; task < 2 * HH; task += 8) {
        int which = task >= HH;
        int h = which ? task - HH : task;
        const float* c = which ? c2 : c1;
        float dot = 0.f;
        for (int j = lane; j < 2 * VV; j += 32) dot += Wg[h * 2 * VV + j] * c[j];
#pragma unroll
        for (int o = 16; o; o >>= 1) dot += __shfl_xor_sync(0xffffffffu, dot, o);
        if (lane == 0) o_s[which * HH + h] = bg[h] + dot;
    }
    __syncthreads();
    if (tid < HH) {
        float hv = bfd[tid];
#pragma unroll 4
        for (int k = 0; k < 2 * HH; k++) hv += Wfd[tid * 2 * HH + k] * o_s[k];
        h_s[tid] = fmaxf(hv, 0.f);
    }
    __syncthreads();
    if (tid == 0) {
        float l = bff[0];
#pragma unroll 5
        for (int j = 0; j < HH; j++) l += Wff[j] * h_s[j];
        out[b] = 1.f / (1.f + expf(-l));
    }
}

// ---------------- launch ----------------
extern "C" void kernel_launch(void* const* d_in, const int* in_sizes, int n_in,
                              void* d_out, int out_size) {
    const float* out1 = (const float*)d_in[0];
    const float* out2 = (const float*)d_in[1];
    const float* Wg  = (const float*)d_in[2];
    const float* bg  = (const float*)d_in[3];
    const float* Wfd = (const float*)d_in[4];
    const float* bfd = (const float*)d_in[5];
    const float* Wff = (const float*)d_in[6];
    const float* bff = (const float*)d_in[7];
    float* out = (float*)d_out;

    dim3 gp(NSPLIT, BB);
    dim3 gp2(NSPLIT, BB, 2);
    meanPartK<<<gp, 192>>>(out1);
    meanRowPartK<<<gp, 256>>>(out2);
    midK<<<TT + BB, 256>>>();
    attK<<<gp2, 256>>>(out1, out2);
    finalK<<<BB, 256>>>(Wg, bg, Wfd, bfd, Wff, bff, out);
}

// round 7
// speedup vs baseline: 1.1453x; 1.1453x over previous
#include <cuda_runtime.h>
#include <math.h>

#define BB 256
#define SS 512
#define VV 768
#define TT 513   // S + mean row
#define HH 50
#define NSPLIT 8
#define SCHUNK 64   // SS / NSPLIT

// ---------------- scratch (device globals; no allocation allowed) ----------------
__device__ __align__(16) float g_mean1[BB * VV];
__device__ __align__(16) float g_mean2[BB * VV];
__device__ __align__(16) float g_part1[NSPLIT * BB * VV];   // sum1 partials
__device__ __align__(16) float g_part2[NSPLIT * BB * VV];   // sum2 partials
__device__ __align__(16) float g_row[BB * TT];              // row[b,t] = mean1[b] . x2[b,t]
__device__ float g_rowsum[NSPLIT * BB];                     // per-chunk sums of row dots
__device__ __align__(16) float g_wy[BB * TT];               // batch-softmax weights
__device__ __align__(16) float g_axpart[NSPLIT * BB * VV];  // online-softmax partial accumulators
__device__ float g_axm[NSPLIT * BB];                        // running max per partial
__device__ float g_axz[NSPLIT * BB];                        // running Z per partial
__device__ __align__(16) float g_aypart[NSPLIT * BB * VV];  // atty partial sums

// ---------------- K1: partial sum of output_1 over s (unroll-8, split accumulators) ----------------
__global__ __launch_bounds__(192) void meanPartK(const float* __restrict__ src) {
    int split = blockIdx.x, b = blockIdx.y, tid = threadIdx.x;  // block = 192 = VV/4
    const float4* s4 = (const float4*)src;
    float4 a0 = make_float4(0.f, 0.f, 0.f, 0.f);
    float4 a1 = make_float4(0.f, 0.f, 0.f, 0.f);
    size_t base = ((size_t)b * SS + (size_t)split * SCHUNK) * (VV / 4) + tid;
    for (int t = 0; t < SCHUNK; t += 8) {
        float4 x[8];
#pragma unroll
        for (int k = 0; k < 8; k++) x[k] = __ldcs(&s4[base + (size_t)(t + k) * (VV / 4)]);
#pragma unroll
        for (int k = 0; k < 8; k += 2) {
            a0.x += x[k].x;   a0.y += x[k].y;   a0.z += x[k].z;   a0.w += x[k].w;
            a1.x += x[k+1].x; a1.y += x[k+1].y; a1.z += x[k+1].z; a1.w += x[k+1].w;
        }
    }
    a0.x += a1.x; a0.y += a1.y; a0.z += a1.z; a0.w += a1.w;
    ((float4*)g_part1)[((size_t)split * BB + b) * (VV / 4) + tid] = a0;
}

// ---------------- K2: fused pass over output_2: sum2 partials + row[b,t] dots + chunk dot-sums ----------------
__global__ __launch_bounds__(256) void meanRowPartK(const float* __restrict__ src) {
    __shared__ __align__(16) float m_s[VV];
    __shared__ __align__(16) float buf[VV];
    __shared__ float sdot[SCHUNK];
    int split = blockIdx.x, b = blockIdx.y, tid = threadIdx.x;
    int wid = tid >> 5, lane = tid & 31;
    // mean1 from partials (L2-hot)
    for (int i = tid; i < VV; i += 256) {
        float s = 0.f;
#pragma unroll
        for (int p = 0; p < NSPLIT; p++) s += g_part1[((size_t)p * BB + b) * VV + i];
        m_s[i] = s * (1.0f / SS);
    }
    __syncthreads();
    const float4* s4 = (const float4*)src;
    const float4* m4 = (const float4*)m_s;
    float4 macc[6];
#pragma unroll
    for (int j = 0; j < 6; j++) macc[j] = make_float4(0.f, 0.f, 0.f, 0.f);
    int t0 = split * SCHUNK;
    for (int i = 0; i < SCHUNK / 8; i++) {
        int t = t0 + wid + 8 * i;
        size_t base = ((size_t)b * SS + t) * (VV / 4);
        float dot = 0.f;
#pragma unroll
        for (int j = 0; j < 6; j++) {
            float4 x = __ldcs(&s4[base + lane + 32 * j]);
            float4 m = m4[lane + 32 * j];
            dot += x.x * m.x + x.y * m.y + x.z * m.z + x.w * m.w;
            macc[j].x += x.x; macc[j].y += x.y; macc[j].z += x.z; macc[j].w += x.w;
        }
#pragma unroll
        for (int o = 16; o; o >>= 1) dot += __shfl_xor_sync(0xffffffffu, dot, o);
        if (lane == 0) { g_row[b * TT + t] = dot; sdot[wid + 8 * i] = dot; }
    }
    // cross-warp reduce of per-lane column partial sums
    float4* b4 = (float4*)buf;
    for (int w = 0; w < 8; w++) {
        if (wid == w) {
#pragma unroll
            for (int j = 0; j < 6; j++) {
                if (w == 0) b4[lane + 32 * j] = macc[j];
                else {
                    float4 t2 = b4[lane + 32 * j];
                    t2.x += macc[j].x; t2.y += macc[j].y; t2.z += macc[j].z; t2.w += macc[j].w;
                    b4[lane + 32 * j] = t2;
                }
            }
        }
        __syncthreads();
    }
    for (int i = tid; i < VV; i += 256) g_part2[((size_t)split * BB + b) * VV + i] = buf[i];
    // chunk sum of the SCHUNK dots -> g_rowsum (for row[b,512] = mean of all dots)
    if (tid < 32) {
        float s = sdot[tid] + sdot[tid + 32];
#pragma unroll
        for (int o = 16; o; o >>= 1) s += __shfl_xor_sync(0xffffffffu, s, o);
        if (tid == 0) g_rowsum[split * BB + b] = s;
    }
}

// ---------------- K3 (fused): blocks [0,513): softmax over batch per t (t=512 builds its row first)
//                              blocks [513,769): materialize mean1/mean2 for b = blk-513 ----------------
__global__ __launch_bounds__(256) void midK() {
    if (blockIdx.x >= TT) {
        int b = blockIdx.x - TT, tid = threadIdx.x;
        for (int i = tid; i < VV; i += 256) {
            float s1 = 0.f, s2 = 0.f;
#pragma unroll
            for (int p = 0; p < NSPLIT; p++) {
                s1 += g_part1[((size_t)p * BB + b) * VV + i];
                s2 += g_part2[((size_t)p * BB + b) * VV + i];
            }
            g_mean1[(size_t)b * VV + i] = s1 * (1.0f / SS);
            g_mean2[(size_t)b * VV + i] = s2 * (1.0f / SS);
        }
        return;
    }
    int t = blockIdx.x;          // [0, TT)
    int b = threadIdx.x;         // block = BB
    __shared__ float red[BB];
    float v;
    if (t == 512) {
        float s = 0.f;
#pragma unroll
        for (int p = 0; p < NSPLIT; p++) s += g_rowsum[p * BB + b];
        v = s * (1.0f / SS);
        g_row[b * TT + 512] = v;   // finalK needs col512
    } else {
        v = g_row[b * TT + t];
    }
    red[b] = v; __syncthreads();
    for (int o = 128; o; o >>= 1) { if (b < o) red[b] = fmaxf(red[b], red[b + o]); __syncthreads(); }
    float m = red[0]; __syncthreads();
    float e = __expf(v - m);
    red[b] = e; __syncthreads();
    for (int o = 128; o; o >>= 1) { if (b < o) red[b] += red[b + o]; __syncthreads(); }
    float Z = red[0];
    g_wy[b * TT + t] = e / Z;
}

// ---------------- K4 (fused): z=0 attx over output_1 (smem-staged online softmax, reg prefetch)
//                              z=1 atty over output_2 (weighted sum, unroll 8) ----------------
__global__ __launch_bounds__(256) void attK(const float* __restrict__ out1, const float* __restrict__ out2) {
    __shared__ __align__(16) float m_s[VV];
    __shared__ __align__(16) float chunk[8 * VV];
    __shared__ float sdots[8];
    int split = blockIdx.x, b = blockIdx.y, tid = threadIdx.x;
    int wid = tid >> 5, lane = tid & 31;

    if (blockIdx.z == 1) {
        // ---- atty: acc[v] += wy[t] * out2[b,t,v] ----
        __shared__ float wy_s[SCHUNK];
        int t0 = split * SCHUNK;
        if (tid < SCHUNK) wy_s[tid] = g_wy[b * TT + t0 + tid];
        __syncthreads();
        if (tid < VV / 4) {
            const float4* s4 = (const float4*)out2;
            float4 a0 = make_float4(0.f, 0.f, 0.f, 0.f);
            float4 a1 = make_float4(0.f, 0.f, 0.f, 0.f);
            size_t base = ((size_t)b * SS + t0) * (VV / 4) + tid;
            for (int t = 0; t < SCHUNK; t += 8) {
                float4 x[8]; float w[8];
#pragma unroll
                for (int k = 0; k < 8; k++) { x[k] = __ldcs(&s4[base + (size_t)(t + k) * (VV / 4)]); w[k] = wy_s[t + k]; }
#pragma unroll
                for (int k = 0; k < 8; k += 2) {
                    a0.x += w[k] * x[k].x;     a0.y += w[k] * x[k].y;     a0.z += w[k] * x[k].z;     a0.w += w[k] * x[k].w;
                    a1.x += w[k+1] * x[k+1].x; a1.y += w[k+1] * x[k+1].y; a1.z += w[k+1] * x[k+1].z; a1.w += w[k+1] * x[k+1].w;
                }
            }
            a0.x += a1.x; a0.y += a1.y; a0.z += a1.z; a0.w += a1.w;
            ((float4*)g_aypart)[((size_t)split * BB + b) * (VV / 4) + tid] = a0;
        }
        return;
    }

    // ---- attx: online softmax over s of (out1[b,s,:] . mean2[b]) with weighted accumulation ----
    for (int i = tid; i < VV; i += 256) m_s[i] = g_mean2[(size_t)b * VV + i];
    __syncthreads();
    const float4* s4 = (const float4*)out1;
    const float4* m4 = (const float4*)m_s;
    float4* ch4 = (float4*)chunk;
    float acc0 = 0.f, acc1 = 0.f, acc2 = 0.f;
    float runmax = -1e30f, Z = 0.f;
    int s0 = split * SCHUNK;

    float4 r[6];
    {   // prefetch chunk 0 (8 rows)
        size_t base = ((size_t)b * SS + s0) * (VV / 4);
#pragma unroll
        for (int k = 0; k < 6; k++) r[k] = __ldcs(&s4[base + tid + 256 * k]);
    }
    for (int c = 0; c < SCHUNK / 8; c++) {
#pragma unroll
        for (int k = 0; k < 6; k++) ch4[tid + 256 * k] = r[k];
        __syncthreads();
        if (c < SCHUNK / 8 - 1) {   // prefetch next chunk while computing this one
            size_t base = ((size_t)b * SS + s0 + (c + 1) * 8) * (VV / 4);
#pragma unroll
            for (int k = 0; k < 6; k++) r[k] = __ldcs(&s4[base + tid + 256 * k]);
        }
        float dot = 0.f;
#pragma unroll
        for (int j = 0; j < 6; j++) {
            float4 x = ((const float4*)chunk)[wid * (VV / 4) + lane + 32 * j];
            float4 m = m4[lane + 32 * j];
            dot += x.x * m.x + x.y * m.y + x.z * m.z + x.w * m.w;
        }
#pragma unroll
        for (int o = 16; o; o >>= 1) dot += __shfl_xor_sync(0xffffffffu, dot, o);
        if (lane == 0) sdots[wid] = dot;
        __syncthreads();
        float cm = sdots[0];
#pragma unroll
        for (int rr = 1; rr < 8; rr++) cm = fmaxf(cm, sdots[rr]);
        float nm = fmaxf(runmax, cm);
        float scale = __expf(runmax - nm);
        float w[8]; float wsum = 0.f;
#pragma unroll
        for (int rr = 0; rr < 8; rr++) { w[rr] = __expf(sdots[rr] - nm); wsum += w[rr]; }
        Z = Z * scale + wsum;
        acc0 *= scale; acc1 *= scale; acc2 *= scale;
#pragma unroll
        for (int rr = 0; rr < 8; rr++) {
            acc0 += w[rr] * chunk[rr * VV + tid];
            acc1 += w[rr] * chunk[rr * VV + tid + 256];
            acc2 += w[rr] * chunk[rr * VV + tid + 512];
        }
        runmax = nm;
        __syncthreads();
    }
    size_t ob = (size_t)split * BB + b;
    g_axpart[ob * VV + tid] = acc0;
    g_axpart[ob * VV + tid + 256] = acc1;
    g_axpart[ob * VV + tid + 512] = acc2;
    if (tid == 0) { g_axm[ob] = runmax; g_axz[ob] = Z; }
}

// ---------------- K5: combine partials + full MLP head ----------------
__global__ __launch_bounds__(256) void finalK(const float* __restrict__ Wg, const float* __restrict__ bg,
                                              const float* __restrict__ Wfd, const float* __restrict__ bfd,
                                              const float* __restrict__ Wff, const float* __restrict__ bff,
                                              float* __restrict__ out) {
    int b = blockIdx.x, tid = threadIdx.x, wid = tid >> 5, lane = tid & 31;
    __shared__ float c1[2 * VV];   // [mean1 , atty]
    __shared__ float c2[2 * VV];   // [mean2 , attx]
    __shared__ float o_s[2 * HH];
    __shared__ float h_s[HH];
    float col512 = g_row[b * TT + 512];
    float wy512 = g_wy[b * TT + 512];
    float m[NSPLIT], z[NSPLIT];
#pragma unroll
    for (int i = 0; i < NSPLIT; i++) { m[i] = g_axm[i * BB + b]; z[i] = g_axz[i * BB + b]; }
    float M = col512;
#pragma unroll
    for (int i = 0; i < NSPLIT; i++) M = fmaxf(M, m[i]);
    float e5 = __expf(col512 - M);
    float Ztot = e5;
    float e[NSPLIT];
#pragma unroll
    for (int i = 0; i < NSPLIT; i++) { e[i] = __expf(m[i] - M); Ztot += e[i] * z[i]; }
    float inv = 1.f / Ztot;
    for (int v = tid; v < VV; v += 256) {
        float m1v = g_mean1[(size_t)b * VV + v];
        float m2v = g_mean2[(size_t)b * VV + v];
        float ax = e5 * m1v;
        float ay = wy512 * m2v;
#pragma unroll
        for (int i = 0; i < NSPLIT; i++) {
            ax += e[i] * g_axpart[((size_t)i * BB + b) * VV + v];
            ay += g_aypart[((size_t)i * BB + b) * VV + v];
        }
        c1[v] = m1v; c1[VV + v] = ay;
        c2[v] = m2v; c2[VV + v] = ax * inv;
    }
    __syncthreads();
    // o1/o2: 100 dot products of length 1536 against Wg rows
    for (int task = wid; task < 2 * HH; task += 8) {
        int which = task >= HH;
        int h = which ? task - HH : task;
        const float* c = which ? c2 : c1;
        float dot = 0.f;
        for (int j = lane; j < 2 * VV; j += 32) dot += Wg[h * 2 * VV + j] * c[j];
#pragma unroll
        for (int o = 16; o; o >>= 1) dot += __shfl_xor_sync(0xffffffffu, dot, o);
        if (lane == 0) o_s[which * HH + h] = bg[h] + dot;
    }
    __syncthreads();
    if (tid < HH) {
        float hv = bfd[tid];
#pragma unroll 4
        for (int k = 0; k < 2 * HH; k++) hv += Wfd[tid * 2 * HH + k] * o_s[k];
        h_s[tid] = fmaxf(hv, 0.f);
    }
    __syncthreads();
    if (tid == 0) {
        float l = bff[0];
#pragma unroll 5
        for (int j = 0; j < HH; j++) l += Wff[j] * h_s[j];
        out[b] = 1.f / (1.f + expf(-l));
    }
}

// ---------------- launch ----------------
extern "C" void kernel_launch(void* const* d_in, const int* in_sizes, int n_in,
                              void* d_out, int out_size) {
    const float* out1 = (const float*)d_in[0];
    const float* out2 = (const float*)d_in[1];
    const float* Wg  = (const float*)d_in[2];
    const float* bg  = (const float*)d_in[3];
    const float* Wfd = (const float*)d_in[4];
    const float* bfd = (const float*)d_in[5];
    const float* Wff = (const float*)d_in[6];
    const float* bff = (const float*)d_in[7];
    float* out = (float*)d_out;

    dim3 gp(NSPLIT, BB);
    dim3 gp2(NSPLIT, BB, 2);
    meanPartK<<<gp, 192>>>(out1);
    meanRowPartK<<<gp, 256>>>(out2);
    midK<<<TT + BB, 256>>>();
    attK<<<gp2, 256>>>(out1, out2);
    finalK<<<BB, 256>>>(Wg, bg, Wfd, bfd, Wff, bff, out);
}